// round 2
// baseline (speedup 1.0000x reference)
#include <cuda_runtime.h>

// Problem constants
static constexpr int B_  = 8;
static constexpr int S_  = 2048;
static constexpr int D_  = 1024;
static constexpr int BD_ = 512;
static constexpr int K_  = 64;
static constexpr int MR_ = B_ * K_;   // 512 rows for the bottleneck GEMMs
static constexpr int MT_ = B_ * S_;   // 16384 token rows

// Scratch (device globals; no allocation allowed)
__device__ float g_inv_tot[B_ * K_];
__device__ float g_gathered[MR_ * D_];      // normalized gather result [B*K, D]
__device__ float g_encoded[MR_ * BD_];      // [B*K, BD]
__device__ float g_transformed[MR_ * BD_];  // [B*K, BD]
__device__ float g_decoded[MR_ * D_];       // [B*K, D]

// ---------------------------------------------------------------------------
// K0: totals[b,k] = 1 / max(sum_s infl[b,s,k], 1e-8)
// grid = B_, block = (64, 8)
// ---------------------------------------------------------------------------
__global__ void totals_kernel(const float* __restrict__ infl) {
    int b = blockIdx.x;
    int k = threadIdx.x;      // 0..63
    int sg = threadIdx.y;     // 0..7
    float acc = 0.f;
    for (int s = sg; s < S_; s += 8)
        acc += infl[((size_t)(b * S_ + s)) * K_ + k];
    __shared__ float red[8][64];
    red[sg][k] = acc;
    __syncthreads();
    if (sg == 0) {
        float t = 0.f;
        #pragma unroll
        for (int i = 0; i < 8; i++) t += red[i][k];
        t = fmaxf(t, 1e-8f);
        g_inv_tot[b * K_ + k] = 1.f / t;
    }
}

// ---------------------------------------------------------------------------
// K1: gathered[b,k,d] = inv_tot[b,k] * sum_s infl[b,s,k] * tok[b,s,d]
// Per-batch GEMM: (K x S) * (S x D), tiled 64(k) x 64(d), s-chunks of 32.
// grid = (D/64, B), block = (16,16)
// ---------------------------------------------------------------------------
__global__ void gather_kernel(const float* __restrict__ tok,
                              const float* __restrict__ infl) {
    int b  = blockIdx.y;
    int d0 = blockIdx.x * 64;
    __shared__ float sI[32][65];   // [s][k]
    __shared__ float sT[32][65];   // [s][d]
    __shared__ float sInv[64];
    int tx = threadIdx.x, ty = threadIdx.y;
    int t = ty * 16 + tx;
    if (t < 64) sInv[t] = g_inv_tot[b * K_ + t];
    float acc[4][4] = {};
    for (int s0 = 0; s0 < S_; s0 += 32) {
        for (int i = t; i < 32 * 64; i += 256) {
            int s = i >> 6, x = i & 63;
            sI[s][x] = infl[((size_t)(b * S_ + s0 + s)) * K_ + x];
            sT[s][x] = tok[((size_t)(b * S_ + s0 + s)) * D_ + d0 + x];
        }
        __syncthreads();
        #pragma unroll 8
        for (int s = 0; s < 32; s++) {
            float a[4], bb[4];
            #pragma unroll
            for (int i = 0; i < 4; i++) a[i] = sI[s][ty + 16 * i];
            #pragma unroll
            for (int j = 0; j < 4; j++) bb[j] = sT[s][tx + 16 * j];
            #pragma unroll
            for (int i = 0; i < 4; i++)
                #pragma unroll
                for (int j = 0; j < 4; j++)
                    acc[i][j] = fmaf(a[i], bb[j], acc[i][j]);
        }
        __syncthreads();
    }
    #pragma unroll
    for (int i = 0; i < 4; i++) {
        int k = ty + 16 * i;
        float inv = sInv[k];
        #pragma unroll
        for (int j = 0; j < 4; j++) {
            int d = d0 + tx + 16 * j;
            g_gathered[((size_t)(b * K_ + k)) * D_ + d] = acc[i][j] * inv;
        }
    }
}

// ---------------------------------------------------------------------------
// K2/K4: generic 64x64-tile SGEMM  C = act(A[M,Kd] * W[Kd,N] + bias)
// grid = (N/64, M/64), block = (16,16). Dims must be multiples of 64/16.
// ---------------------------------------------------------------------------
__global__ void gemm64_kernel(const float* __restrict__ A,
                              const float* __restrict__ W,
                              const float* __restrict__ bias,
                              float* __restrict__ C,
                              int M, int N, int Kd, int doRelu) {
    __shared__ float sA[16][65];   // [kk][m]
    __shared__ float sB[16][65];   // [kk][n]
    int n0 = blockIdx.x * 64, m0 = blockIdx.y * 64;
    int tx = threadIdx.x, ty = threadIdx.y;
    int t = ty * 16 + tx;
    float acc[4][4] = {};
    for (int k0 = 0; k0 < Kd; k0 += 16) {
        for (int i = t; i < 16 * 64; i += 256) {
            int kk = i & 15, m = i >> 4;
            sA[kk][m] = A[(size_t)(m0 + m) * Kd + k0 + kk];
        }
        for (int i = t; i < 16 * 64; i += 256) {
            int kk = i >> 6, n = i & 63;
            sB[kk][n] = W[(size_t)(k0 + kk) * N + n0 + n];
        }
        __syncthreads();
        #pragma unroll
        for (int kk = 0; kk < 16; kk++) {
            float a[4], bb[4];
            #pragma unroll
            for (int i = 0; i < 4; i++) a[i] = sA[kk][ty + 16 * i];
            #pragma unroll
            for (int j = 0; j < 4; j++) bb[j] = sB[kk][tx + 16 * j];
            #pragma unroll
            for (int i = 0; i < 4; i++)
                #pragma unroll
                for (int j = 0; j < 4; j++)
                    acc[i][j] = fmaf(a[i], bb[j], acc[i][j]);
        }
        __syncthreads();
    }
    #pragma unroll
    for (int j = 0; j < 4; j++) {
        int n = n0 + tx + 16 * j;
        float bv = bias[n];
        #pragma unroll
        for (int i = 0; i < 4; i++) {
            int m = m0 + ty + 16 * i;
            float v = acc[i][j] + bv;
            if (doRelu) v = fmaxf(v, 0.f);
            C[(size_t)m * N + n] = v;
        }
    }
}

// ---------------------------------------------------------------------------
// K3: transformed[b,k,:] = encoded[b,k,:] @ trans_W[k] + trans_b[k]
// One block per (n-tile of 64, splat k). Streams trans_W exactly once.
// grid = (BD/64, K), block = 256
// ---------------------------------------------------------------------------
__global__ void transform_kernel(const float* __restrict__ trans_W,
                                 const float* __restrict__ trans_b) {
    int k  = blockIdx.y;
    int n0 = blockIdx.x * 64;
    __shared__ float sE[8][33];    // [b][e]
    __shared__ float sW[32][65];   // [e][n]
    int t = threadIdx.x;
    int n = t & 63;
    int bq = t >> 6;               // 0..3 -> handles rows 2*bq, 2*bq+1
    float c0 = 0.f, c1 = 0.f;
    for (int e0 = 0; e0 < BD_; e0 += 32) {
        {
            int bb = t >> 5, e = t & 31;   // 8 rows x 32 cols, one per thread
            sE[bb][e] = g_encoded[((size_t)(bb * K_ + k)) * BD_ + e0 + e];
        }
        for (int i = t; i < 32 * 64; i += 256) {
            int e = i >> 6, x = i & 63;
            sW[e][x] = trans_W[((size_t)k * BD_ + e0 + e) * BD_ + n0 + x];
        }
        __syncthreads();
        #pragma unroll 8
        for (int e = 0; e < 32; e++) {
            float w = sW[e][n];
            c0 = fmaf(sE[2 * bq][e],     w, c0);
            c1 = fmaf(sE[2 * bq + 1][e], w, c1);
        }
        __syncthreads();
    }
    float tb = trans_b[k * BD_ + n0 + n];
    g_transformed[((size_t)((2 * bq) * K_ + k)) * BD_ + n0 + n]     = c0 + tb;
    g_transformed[((size_t)((2 * bq + 1) * K_ + k)) * BD_ + n0 + n] = c1 + tb;
}

// ---------------------------------------------------------------------------
// K5a: out[m,n] = sigmoid(tok[m,:] @ gate_W[:,n] + gate_b[n])
// 128x128x8 SGEMM, float4 global loads, transposed-A smem. grid=(8,128), 256 thr
// ---------------------------------------------------------------------------
__global__ void __launch_bounds__(256)
gate_kernel(const float* __restrict__ tok,
            const float* __restrict__ gate_W,
            const float* __restrict__ gate_b,
            float* __restrict__ out) {
    __shared__ float sA[8][132];   // [kk][m], padded to kill store conflicts
    __shared__ float sB[8][128];   // [kk][n]
    int n0 = blockIdx.x * 128, m0 = blockIdx.y * 128;
    int tx = threadIdx.x, ty = threadIdx.y;
    int t = ty * 16 + tx;
    int arow = t >> 1, acol = (t & 1) * 4;     // A tile: 128 x 8, float4
    int brow = t >> 5, bcol = (t & 31) * 4;    // B tile: 8 x 128, float4
    float acc[8][8] = {};
    for (int k0 = 0; k0 < D_; k0 += 8) {
        float4 av = *(const float4*)(tok    + (size_t)(m0 + arow) * D_ + k0 + acol);
        float4 bv = *(const float4*)(gate_W + (size_t)(k0 + brow) * D_ + n0 + bcol);
        __syncthreads();
        sA[acol + 0][arow] = av.x;
        sA[acol + 1][arow] = av.y;
        sA[acol + 2][arow] = av.z;
        sA[acol + 3][arow] = av.w;
        *(float4*)(&sB[brow][bcol]) = bv;
        __syncthreads();
        #pragma unroll
        for (int kk = 0; kk < 8; kk++) {
            float a[8], bb[8];
            #pragma unroll
            for (int i = 0; i < 8; i++) a[i] = sA[kk][ty + 16 * i];
            #pragma unroll
            for (int j = 0; j < 8; j++) bb[j] = sB[kk][tx + 16 * j];
            #pragma unroll
            for (int i = 0; i < 8; i++)
                #pragma unroll
                for (int j = 0; j < 8; j++)
                    acc[i][j] = fmaf(a[i], bb[j], acc[i][j]);
        }
    }
    #pragma unroll
    for (int j = 0; j < 8; j++) {
        int n = n0 + tx + 16 * j;
        float gb = gate_b[n];
        #pragma unroll
        for (int i = 0; i < 8; i++) {
            int m = m0 + ty + 16 * i;
            float g = acc[i][j] + gb;
            out[(size_t)m * D_ + n] = 1.f / (1.f + __expf(-g));
        }
    }
}

// ---------------------------------------------------------------------------
// K5b: out[m,n] *= sum_k infl[m,k] * decoded[b,k,n], b = m / S
// 64x64 output tile, full K=64 inner dim in smem. grid=(16,256), block=(16,16)
// ---------------------------------------------------------------------------
__global__ void flow_kernel(const float* __restrict__ infl,
                            float* __restrict__ out) {
    __shared__ float sI[64][65];   // [m][k]
    __shared__ float sD[64][65];   // [k][n]
    int n0 = blockIdx.x * 64;
    int m0 = blockIdx.y * 64;
    int b  = m0 / S_;              // 64 | 2048, so constant per block
    int tx = threadIdx.x, ty = threadIdx.y;
    int t = ty * 16 + tx;
    for (int i = t; i < 64 * 64; i += 256) {
        int m = i >> 6, k = i & 63;
        sI[m][k] = infl[(size_t)(m0 + m) * K_ + k];
    }
    for (int i = t; i < 64 * 64; i += 256) {
        int k = i >> 6, n = i & 63;
        sD[k][n] = g_decoded[((size_t)(b * K_ + k)) * D_ + n0 + n];
    }
    __syncthreads();
    float acc[4][4] = {};
    #pragma unroll 8
    for (int k = 0; k < 64; k++) {
        float a[4], bb[4];
        #pragma unroll
        for (int i = 0; i < 4; i++) a[i] = sI[ty + 16 * i][k];
        #pragma unroll
        for (int j = 0; j < 4; j++) bb[j] = sD[k][tx + 16 * j];
        #pragma unroll
        for (int i = 0; i < 4; i++)
            #pragma unroll
            for (int j = 0; j < 4; j++)
                acc[i][j] = fmaf(a[i], bb[j], acc[i][j]);
    }
    #pragma unroll
    for (int i = 0; i < 4; i++) {
        #pragma unroll
        for (int j = 0; j < 4; j++) {
            size_t idx = (size_t)(m0 + ty + 16 * i) * D_ + n0 + tx + 16 * j;
            out[idx] = out[idx] * acc[i][j];
        }
    }
}

// ---------------------------------------------------------------------------
extern "C" void kernel_launch(void* const* d_in, const int* in_sizes, int n_in,
                              void* d_out, int out_size) {
    const float* tok     = (const float*)d_in[0];
    const float* infl    = (const float*)d_in[1];
    const float* enc_W   = (const float*)d_in[2];
    const float* enc_b   = (const float*)d_in[3];
    const float* trans_W = (const float*)d_in[4];
    const float* trans_b = (const float*)d_in[5];
    const float* dec_W   = (const float*)d_in[6];
    const float* dec_b   = (const float*)d_in[7];
    const float* gate_W  = (const float*)d_in[8];
    const float* gate_b  = (const float*)d_in[9];
    float* out = (float*)d_out;

    void *pG, *pE, *pT, *pD;
    cudaGetSymbolAddress(&pG, g_gathered);
    cudaGetSymbolAddress(&pE, g_encoded);
    cudaGetSymbolAddress(&pT, g_transformed);
    cudaGetSymbolAddress(&pD, g_decoded);
    float* gath = (float*)pG;
    float* enc  = (float*)pE;
    float* trns = (float*)pT;
    float* dec  = (float*)pD;

    totals_kernel<<<B_, dim3(64, 8)>>>(infl);
    gather_kernel<<<dim3(D_ / 64, B_), dim3(16, 16)>>>(tok, infl);
    // encoder: [512,1024] @ [1024,512] + relu
    gemm64_kernel<<<dim3(BD_ / 64, MR_ / 64), dim3(16, 16)>>>(
        gath, enc_W, enc_b, enc, MR_, BD_, D_, 1);
    // per-splat transform
    transform_kernel<<<dim3(BD_ / 64, K_), 256>>>(trans_W, trans_b);
    // decoder: [512,512] @ [512,1024]
    gemm64_kernel<<<dim3(D_ / 64, MR_ / 64), dim3(16, 16)>>>(
        trns, dec_W, dec_b, dec, MR_, D_, BD_, 0);
    // gate GEMM + sigmoid into d_out
    gate_kernel<<<dim3(D_ / 128, MT_ / 128), dim3(16, 16)>>>(
        tok, gate_W, gate_b, out);
    // scatter (flow) and multiply into d_out
    flow_kernel<<<dim3(D_ / 64, MT_ / 64), dim3(16, 16)>>>(infl, out);
}

// round 3
// speedup vs baseline: 1.0000x; 1.0000x over previous
#include <cuda_runtime.h>

// Problem constants
static constexpr int B_  = 8;
static constexpr int S_  = 2048;
static constexpr int D_  = 1024;
static constexpr int BD_ = 512;
static constexpr int K_  = 64;
static constexpr int MR_ = B_ * K_;   // 512 rows for the bottleneck GEMMs
static constexpr int MT_ = B_ * S_;   // 16384 token rows

// Scratch (device globals; no allocation allowed)
__device__ float g_inv_tot[B_ * K_];
__device__ float g_gathered[MR_ * D_];      // normalized gather result [B*K, D]
__device__ float g_encoded[MR_ * BD_];      // [B*K, BD]
__device__ float g_transformed[MR_ * BD_];  // [B*K, BD]
__device__ float g_decoded[MR_ * D_];       // [B*K, D]

// ---------------------------------------------------------------------------
// K0: totals[b,k] = 1 / max(sum_s infl[b,s,k], 1e-8)
// grid = B_, block = (64, 8)
// ---------------------------------------------------------------------------
__global__ void totals_kernel(const float* __restrict__ infl) {
    int b = blockIdx.x;
    int k = threadIdx.x;      // 0..63
    int sg = threadIdx.y;     // 0..7
    float acc = 0.f;
    for (int s = sg; s < S_; s += 8)
        acc += infl[((size_t)(b * S_ + s)) * K_ + k];
    __shared__ float red[8][64];
    red[sg][k] = acc;
    __syncthreads();
    if (sg == 0) {
        float t = 0.f;
        #pragma unroll
        for (int i = 0; i < 8; i++) t += red[i][k];
        t = fmaxf(t, 1e-8f);
        g_inv_tot[b * K_ + k] = 1.f / t;
    }
}

// ---------------------------------------------------------------------------
// K1: gathered[b,k,d] = inv_tot[b,k] * sum_s infl[b,s,k] * tok[b,s,d]
// Per-batch GEMM: (K x S) * (S x D), tiled 64(k) x 64(d), s-chunks of 32.
// grid = (D/64, B), block = (16,16)
// ---------------------------------------------------------------------------
__global__ void gather_kernel(const float* __restrict__ tok,
                              const float* __restrict__ infl) {
    int b  = blockIdx.y;
    int d0 = blockIdx.x * 64;
    __shared__ float sI[32][65];   // [s][k]
    __shared__ float sT[32][65];   // [s][d]
    __shared__ float sInv[64];
    int tx = threadIdx.x, ty = threadIdx.y;
    int t = ty * 16 + tx;
    if (t < 64) sInv[t] = g_inv_tot[b * K_ + t];
    float acc[4][4] = {};
    for (int s0 = 0; s0 < S_; s0 += 32) {
        for (int i = t; i < 32 * 64; i += 256) {
            int s = i >> 6, x = i & 63;
            sI[s][x] = infl[((size_t)(b * S_ + s0 + s)) * K_ + x];
            sT[s][x] = tok[((size_t)(b * S_ + s0 + s)) * D_ + d0 + x];
        }
        __syncthreads();
        #pragma unroll 8
        for (int s = 0; s < 32; s++) {
            float a[4], bb[4];
            #pragma unroll
            for (int i = 0; i < 4; i++) a[i] = sI[s][ty + 16 * i];
            #pragma unroll
            for (int j = 0; j < 4; j++) bb[j] = sT[s][tx + 16 * j];
            #pragma unroll
            for (int i = 0; i < 4; i++)
                #pragma unroll
                for (int j = 0; j < 4; j++)
                    acc[i][j] = fmaf(a[i], bb[j], acc[i][j]);
        }
        __syncthreads();
    }
    #pragma unroll
    for (int i = 0; i < 4; i++) {
        int k = ty + 16 * i;
        float inv = sInv[k];
        #pragma unroll
        for (int j = 0; j < 4; j++) {
            int d = d0 + tx + 16 * j;
            g_gathered[((size_t)(b * K_ + k)) * D_ + d] = acc[i][j] * inv;
        }
    }
}

// ---------------------------------------------------------------------------
// K2/K4: generic 64x64-tile SGEMM  C = act(A[M,Kd] * W[Kd,N] + bias)
// grid = (N/64, M/64), block = (16,16). Dims must be multiples of 64/16.
// ---------------------------------------------------------------------------
__global__ void gemm64_kernel(const float* __restrict__ A,
                              const float* __restrict__ W,
                              const float* __restrict__ bias,
                              float* __restrict__ C,
                              int M, int N, int Kd, int doRelu) {
    __shared__ float sA[16][65];   // [kk][m]
    __shared__ float sB[16][65];   // [kk][n]
    int n0 = blockIdx.x * 64, m0 = blockIdx.y * 64;
    int tx = threadIdx.x, ty = threadIdx.y;
    int t = ty * 16 + tx;
    float acc[4][4] = {};
    for (int k0 = 0; k0 < Kd; k0 += 16) {
        for (int i = t; i < 16 * 64; i += 256) {
            int kk = i & 15, m = i >> 4;
            sA[kk][m] = A[(size_t)(m0 + m) * Kd + k0 + kk];
        }
        for (int i = t; i < 16 * 64; i += 256) {
            int kk = i >> 6, n = i & 63;
            sB[kk][n] = W[(size_t)(k0 + kk) * N + n0 + n];
        }
        __syncthreads();
        #pragma unroll
        for (int kk = 0; kk < 16; kk++) {
            float a[4], bb[4];
            #pragma unroll
            for (int i = 0; i < 4; i++) a[i] = sA[kk][ty + 16 * i];
            #pragma unroll
            for (int j = 0; j < 4; j++) bb[j] = sB[kk][tx + 16 * j];
            #pragma unroll
            for (int i = 0; i < 4; i++)
                #pragma unroll
                for (int j = 0; j < 4; j++)
                    acc[i][j] = fmaf(a[i], bb[j], acc[i][j]);
        }
        __syncthreads();
    }
    #pragma unroll
    for (int j = 0; j < 4; j++) {
        int n = n0 + tx + 16 * j;
        float bv = bias[n];
        #pragma unroll
        for (int i = 0; i < 4; i++) {
            int m = m0 + ty + 16 * i;
            float v = acc[i][j] + bv;
            if (doRelu) v = fmaxf(v, 0.f);
            C[(size_t)m * N + n] = v;
        }
    }
}

// ---------------------------------------------------------------------------
// K3: transformed[b,k,:] = encoded[b,k,:] @ trans_W[k] + trans_b[k]
// One block per (n-tile of 64, splat k). Streams trans_W exactly once.
// grid = (BD/64, K), block = 256
// ---------------------------------------------------------------------------
__global__ void transform_kernel(const float* __restrict__ trans_W,
                                 const float* __restrict__ trans_b) {
    int k  = blockIdx.y;
    int n0 = blockIdx.x * 64;
    __shared__ float sE[8][33];    // [b][e]
    __shared__ float sW[32][65];   // [e][n]
    int t = threadIdx.x;
    int n = t & 63;
    int bq = t >> 6;               // 0..3 -> handles rows 2*bq, 2*bq+1
    float c0 = 0.f, c1 = 0.f;
    for (int e0 = 0; e0 < BD_; e0 += 32) {
        {
            int bb = t >> 5, e = t & 31;   // 8 rows x 32 cols, one per thread
            sE[bb][e] = g_encoded[((size_t)(bb * K_ + k)) * BD_ + e0 + e];
        }
        for (int i = t; i < 32 * 64; i += 256) {
            int e = i >> 6, x = i & 63;
            sW[e][x] = trans_W[((size_t)k * BD_ + e0 + e) * BD_ + n0 + x];
        }
        __syncthreads();
        #pragma unroll 8
        for (int e = 0; e < 32; e++) {
            float w = sW[e][n];
            c0 = fmaf(sE[2 * bq][e],     w, c0);
            c1 = fmaf(sE[2 * bq + 1][e], w, c1);
        }
        __syncthreads();
    }
    float tb = trans_b[k * BD_ + n0 + n];
    g_transformed[((size_t)((2 * bq) * K_ + k)) * BD_ + n0 + n]     = c0 + tb;
    g_transformed[((size_t)((2 * bq + 1) * K_ + k)) * BD_ + n0 + n] = c1 + tb;
}

// ---------------------------------------------------------------------------
// K5a: out[m,n] = sigmoid(tok[m,:] @ gate_W[:,n] + gate_b[n])
// 128x128x8 SGEMM, float4 global loads, transposed-A smem. grid=(8,128), 256 thr
// ---------------------------------------------------------------------------
__global__ void __launch_bounds__(256)
gate_kernel(const float* __restrict__ tok,
            const float* __restrict__ gate_W,
            const float* __restrict__ gate_b,
            float* __restrict__ out) {
    __shared__ float sA[8][132];   // [kk][m], padded to kill store conflicts
    __shared__ float sB[8][128];   // [kk][n]
    int n0 = blockIdx.x * 128, m0 = blockIdx.y * 128;
    int tx = threadIdx.x, ty = threadIdx.y;
    int t = ty * 16 + tx;
    int arow = t >> 1, acol = (t & 1) * 4;     // A tile: 128 x 8, float4
    int brow = t >> 5, bcol = (t & 31) * 4;    // B tile: 8 x 128, float4
    float acc[8][8] = {};
    for (int k0 = 0; k0 < D_; k0 += 8) {
        float4 av = *(const float4*)(tok    + (size_t)(m0 + arow) * D_ + k0 + acol);
        float4 bv = *(const float4*)(gate_W + (size_t)(k0 + brow) * D_ + n0 + bcol);
        __syncthreads();
        sA[acol + 0][arow] = av.x;
        sA[acol + 1][arow] = av.y;
        sA[acol + 2][arow] = av.z;
        sA[acol + 3][arow] = av.w;
        *(float4*)(&sB[brow][bcol]) = bv;
        __syncthreads();
        #pragma unroll
        for (int kk = 0; kk < 8; kk++) {
            float a[8], bb[8];
            #pragma unroll
            for (int i = 0; i < 8; i++) a[i] = sA[kk][ty + 16 * i];
            #pragma unroll
            for (int j = 0; j < 8; j++) bb[j] = sB[kk][tx + 16 * j];
            #pragma unroll
            for (int i = 0; i < 8; i++)
                #pragma unroll
                for (int j = 0; j < 8; j++)
                    acc[i][j] = fmaf(a[i], bb[j], acc[i][j]);
        }
    }
    #pragma unroll
    for (int j = 0; j < 8; j++) {
        int n = n0 + tx + 16 * j;
        float gb = gate_b[n];
        #pragma unroll
        for (int i = 0; i < 8; i++) {
            int m = m0 + ty + 16 * i;
            float g = acc[i][j] + gb;
            out[(size_t)m * D_ + n] = 1.f / (1.f + __expf(-g));
        }
    }
}

// ---------------------------------------------------------------------------
// K5b: out[m,n] *= sum_k infl[m,k] * decoded[b,k,n], b = m / S
// 64x64 output tile, full K=64 inner dim in smem. grid=(16,256), block=(16,16)
// ---------------------------------------------------------------------------
__global__ void flow_kernel(const float* __restrict__ infl,
                            float* __restrict__ out) {
    __shared__ float sI[64][65];   // [m][k]
    __shared__ float sD[64][65];   // [k][n]
    int n0 = blockIdx.x * 64;
    int m0 = blockIdx.y * 64;
    int b  = m0 / S_;              // 64 | 2048, so constant per block
    int tx = threadIdx.x, ty = threadIdx.y;
    int t = ty * 16 + tx;
    for (int i = t; i < 64 * 64; i += 256) {
        int m = i >> 6, k = i & 63;
        sI[m][k] = infl[(size_t)(m0 + m) * K_ + k];
    }
    for (int i = t; i < 64 * 64; i += 256) {
        int k = i >> 6, n = i & 63;
        sD[k][n] = g_decoded[((size_t)(b * K_ + k)) * D_ + n0 + n];
    }
    __syncthreads();
    float acc[4][4] = {};
    #pragma unroll 8
    for (int k = 0; k < 64; k++) {
        float a[4], bb[4];
        #pragma unroll
        for (int i = 0; i < 4; i++) a[i] = sI[ty + 16 * i][k];
        #pragma unroll
        for (int j = 0; j < 4; j++) bb[j] = sD[k][tx + 16 * j];
        #pragma unroll
        for (int i = 0; i < 4; i++)
            #pragma unroll
            for (int j = 0; j < 4; j++)
                acc[i][j] = fmaf(a[i], bb[j], acc[i][j]);
    }
    #pragma unroll
    for (int i = 0; i < 4; i++) {
        #pragma unroll
        for (int j = 0; j < 4; j++) {
            size_t idx = (size_t)(m0 + ty + 16 * i) * D_ + n0 + tx + 16 * j;
            out[idx] = out[idx] * acc[i][j];
        }
    }
}

// ---------------------------------------------------------------------------
extern "C" void kernel_launch(void* const* d_in, const int* in_sizes, int n_in,
                              void* d_out, int out_size) {
    const float* tok     = (const float*)d_in[0];
    const float* infl    = (const float*)d_in[1];
    const float* enc_W   = (const float*)d_in[2];
    const float* enc_b   = (const float*)d_in[3];
    const float* trans_W = (const float*)d_in[4];
    const float* trans_b = (const float*)d_in[5];
    const float* dec_W   = (const float*)d_in[6];
    const float* dec_b   = (const float*)d_in[7];
    const float* gate_W  = (const float*)d_in[8];
    const float* gate_b  = (const float*)d_in[9];
    float* out = (float*)d_out;

    void *pG, *pE, *pT, *pD;
    cudaGetSymbolAddress(&pG, g_gathered);
    cudaGetSymbolAddress(&pE, g_encoded);
    cudaGetSymbolAddress(&pT, g_transformed);
    cudaGetSymbolAddress(&pD, g_decoded);
    float* gath = (float*)pG;
    float* enc  = (float*)pE;
    float* trns = (float*)pT;
    float* dec  = (float*)pD;

    totals_kernel<<<B_, dim3(64, 8)>>>(infl);
    gather_kernel<<<dim3(D_ / 64, B_), dim3(16, 16)>>>(tok, infl);
    // encoder: [512,1024] @ [1024,512] + relu
    gemm64_kernel<<<dim3(BD_ / 64, MR_ / 64), dim3(16, 16)>>>(
        gath, enc_W, enc_b, enc, MR_, BD_, D_, 1);
    // per-splat transform
    transform_kernel<<<dim3(BD_ / 64, K_), 256>>>(trans_W, trans_b);
    // decoder: [512,512] @ [512,1024]
    gemm64_kernel<<<dim3(D_ / 64, MR_ / 64), dim3(16, 16)>>>(
        trns, dec_W, dec_b, dec, MR_, D_, BD_, 0);
    // gate GEMM + sigmoid into d_out
    gate_kernel<<<dim3(D_ / 128, MT_ / 128), dim3(16, 16)>>>(
        tok, gate_W, gate_b, out);
    // scatter (flow) and multiply into d_out
    flow_kernel<<<dim3(D_ / 64, MT_ / 64), dim3(16, 16)>>>(infl, out);
}